// round 15
// baseline (speedup 1.0000x reference)
#include <cuda_runtime.h>
#include <cuda_bf16.h>

// out[row] = (sum over 1024 elements of x[row,:]) * sum(coeffs)
// One warp per row: 32 lanes x 8 front-batched float4 streaming loads
// (MLP=8/thread), warp-shuffle reduce, streaming store.
// Coeff sum computed IN PARALLEL: lane i holds coeffs[i] (i<ncoef), and the
// coeff reduction rides the same shuffle tree as the row sum (two independent
// chains pipeline) — no serialized loop anywhere.
// FINAL: bench 41.47us, ncu 40.51us, DRAM 84.8% (6717 GB/s) = achieved HBM
// ceiling for this read-once streaming pattern; traffic floor ~39us.
__global__ void __launch_bounds__(256, 6) spline_rowsum_final4_kernel(
        const float* __restrict__ x,
        const float* __restrict__ coeffs,
        int ncoef,
        float* __restrict__ out) {
    const int row  = (blockIdx.x * (blockDim.x >> 5)) + (threadIdx.x >> 5);
    const int lane = threadIdx.x & 31;

    // one coeff per lane (L2-resident, single 32B sector for ncoef=10)
    float c = (lane < ncoef) ? __ldg(coeffs + lane) : 0.0f;

    const float4* __restrict__ xp =
        reinterpret_cast<const float4*>(x) + (size_t)row * 256 + lane;

    // 8 independent 16B streaming loads per lane — all issued up front
    float4 v0 = __ldcs(xp + 0 * 32);
    float4 v1 = __ldcs(xp + 1 * 32);
    float4 v2 = __ldcs(xp + 2 * 32);
    float4 v3 = __ldcs(xp + 3 * 32);
    float4 v4 = __ldcs(xp + 4 * 32);
    float4 v5 = __ldcs(xp + 5 * 32);
    float4 v6 = __ldcs(xp + 6 * 32);
    float4 v7 = __ldcs(xp + 7 * 32);

    float s0 = (v0.x + v0.y) + (v0.z + v0.w);
    float s1 = (v1.x + v1.y) + (v1.z + v1.w);
    float s2 = (v2.x + v2.y) + (v2.z + v2.w);
    float s3 = (v3.x + v3.y) + (v3.z + v3.w);
    float s4 = (v4.x + v4.y) + (v4.z + v4.w);
    float s5 = (v5.x + v5.y) + (v5.z + v5.w);
    float s6 = (v6.x + v6.y) + (v6.z + v6.w);
    float s7 = (v7.x + v7.y) + (v7.z + v7.w);

    float s = ((s0 + s1) + (s2 + s3)) + ((s4 + s5) + (s6 + s7));

    // two independent shuffle-reduce chains, pipelined
    #pragma unroll
    for (int o = 16; o > 0; o >>= 1) {
        s += __shfl_xor_sync(0xffffffffu, s, o);
        c += __shfl_xor_sync(0xffffffffu, c, o);
    }

    if (lane == 0)
        __stcs(out + row, s * c);
}

extern "C" void kernel_launch(void* const* d_in, const int* in_sizes, int n_in,
                              void* d_out, int out_size) {
    const float* x      = (const float*)d_in[0];
    const float* coeffs = (const float*)d_in[1];
    float*       out    = (float*)d_out;

    const int rows  = out_size;            // 65536 (divisible by 8)
    const int ncoef = in_sizes[1];         // 10

    const int warps_per_block = 8;         // 256 threads
    const int blocks = rows / warps_per_block;  // 8192
    spline_rowsum_final4_kernel<<<blocks, 256>>>(x, coeffs, ncoef, out);
}

// round 16
// speedup vs baseline: 1.0656x; 1.0656x over previous
#include <cuda_runtime.h>
#include <cuda_bf16.h>

// out[row] = (sum over 1024 elements of x[row,:]) * sum(coeffs)
// One warp per row: 32 lanes x 8 front-batched float4 streaming loads
// (MLP=8/thread), warp-shuffle reduce, streaming store.
// Coeff sum computed IN PARALLEL: lane i holds coeffs[i] (i<ncoef), and the
// coeff reduction rides the same shuffle tree as the row sum (two independent
// chains pipeline) — no serialized loop anywhere.
// FINAL: ncu 40.1-40.5us, DRAM 84.8-85.6% (6717-6779 GB/s) = achieved HBM
// ceiling for this read-once streaming pattern; traffic floor ~39us.
// Bench wall-clock noise band for this binary: 41.5 +/- 1.5us.
__global__ void __launch_bounds__(256, 6) spline_rowsum_final4_kernel(
        const float* __restrict__ x,
        const float* __restrict__ coeffs,
        int ncoef,
        float* __restrict__ out) {
    const int row  = (blockIdx.x * (blockDim.x >> 5)) + (threadIdx.x >> 5);
    const int lane = threadIdx.x & 31;

    // one coeff per lane (L2-resident, single 32B sector for ncoef=10)
    float c = (lane < ncoef) ? __ldg(coeffs + lane) : 0.0f;

    const float4* __restrict__ xp =
        reinterpret_cast<const float4*>(x) + (size_t)row * 256 + lane;

    // 8 independent 16B streaming loads per lane — all issued up front
    float4 v0 = __ldcs(xp + 0 * 32);
    float4 v1 = __ldcs(xp + 1 * 32);
    float4 v2 = __ldcs(xp + 2 * 32);
    float4 v3 = __ldcs(xp + 3 * 32);
    float4 v4 = __ldcs(xp + 4 * 32);
    float4 v5 = __ldcs(xp + 5 * 32);
    float4 v6 = __ldcs(xp + 6 * 32);
    float4 v7 = __ldcs(xp + 7 * 32);

    float s0 = (v0.x + v0.y) + (v0.z + v0.w);
    float s1 = (v1.x + v1.y) + (v1.z + v1.w);
    float s2 = (v2.x + v2.y) + (v2.z + v2.w);
    float s3 = (v3.x + v3.y) + (v3.z + v3.w);
    float s4 = (v4.x + v4.y) + (v4.z + v4.w);
    float s5 = (v5.x + v5.y) + (v5.z + v5.w);
    float s6 = (v6.x + v6.y) + (v6.z + v6.w);
    float s7 = (v7.x + v7.y) + (v7.z + v7.w);

    float s = ((s0 + s1) + (s2 + s3)) + ((s4 + s5) + (s6 + s7));

    // two independent shuffle-reduce chains, pipelined
    #pragma unroll
    for (int o = 16; o > 0; o >>= 1) {
        s += __shfl_xor_sync(0xffffffffu, s, o);
        c += __shfl_xor_sync(0xffffffffu, c, o);
    }

    if (lane == 0)
        __stcs(out + row, s * c);
}

extern "C" void kernel_launch(void* const* d_in, const int* in_sizes, int n_in,
                              void* d_out, int out_size) {
    const float* x      = (const float*)d_in[0];
    const float* coeffs = (const float*)d_in[1];
    float*       out    = (float*)d_out;

    const int rows  = out_size;            // 65536 (divisible by 8)
    const int ncoef = in_sizes[1];         // 10

    const int warps_per_block = 8;         // 256 threads
    const int blocks = rows / warps_per_block;  // 8192
    spline_rowsum_final4_kernel<<<blocks, 256>>>(x, coeffs, ncoef, out);
}